// round 15
// baseline (speedup 1.0000x reference)
#include <cuda_runtime.h>

// Problem constants (fixed by the reference)
#define C_CELLS 500000
#define NB 10
#define BLOCK 64
// 4 threads per cell, one float4 of quadrature points each.
// 2,000,000 threads = 31250 blocks of 64 exactly (no ragged block).
#define GRID 31250

__global__ __launch_bounds__(BLOCK)
void quad_fn_kernel(
    const float*  __restrict__ vertex_dofs,     // [V,1]
    const float2* __restrict__ edge_dofs,       // [E,2]
    const float*  __restrict__ face_dofs,       // [C,1]
    const float4* __restrict__ y,               // [C,NB,16] as float4 [C*40]
    const int*    __restrict__ faces,           // [C,3]
    const int*    __restrict__ faces_to_edges,  // [C,3]
    const int*    __restrict__ edge_orientation,// [C,3]
    float4*       __restrict__ out)             // [C,16] as float4 [C*4]
{
    const int gid = blockIdx.x * BLOCK + threadIdx.x;
    const int c  = gid >> 2;          // cell
    const int qg = gid & 3;           // which float4 of the 16 q-points
    if (c >= C_CELLS) return;         // never taken (exact divide), keeps safety

    // ---- Gather local dofs (identical across the 4 lanes of this cell;
    //      LSU coalesces duplicates into broadcast transactions) ----
    float d[NB];

    const int base3 = c * 3;
    #pragma unroll
    for (int i = 0; i < 3; ++i) {
        d[i] = __ldg(&vertex_dofs[__ldg(&faces[base3 + i])]);
    }
    #pragma unroll
    for (int i = 0; i < 3; ++i) {
        const int    e  = __ldg(&faces_to_edges[base3 + i]);
        const float2 ed = __ldg(&edge_dofs[e]);
        const int    o  = __ldg(&edge_orientation[base3 + i]);
        // orientation==1: keep (e0,e1); orientation==0: flipped (e1,e0)
        d[3 + 2 * i]     = o ? ed.x : ed.y;
        d[3 + 2 * i + 1] = o ? ed.y : ed.x;
    }
    d[9] = __ldg(&face_dofs[c]);

    // ---- Weighted sum over basis functions on a float4 of q-points.
    //      y is a zero-reuse 320MB stream: .cg (no L1 allocate). ----
    const float4* yp = y + (size_t)c * (NB * 4) + qg;

    float4 acc = make_float4(0.f, 0.f, 0.f, 0.f);
    #pragma unroll
    for (int b = 0; b < NB; ++b) {
        const float4 v = __ldcg(&yp[b * 4]);
        const float  w = d[b];
        acc.x = fmaf(w, v.x, acc.x);
        acc.y = fmaf(w, v.y, acc.y);
        acc.z = fmaf(w, v.z, acc.z);
        acc.w = fmaf(w, v.w, acc.w);
    }

    __stcg(out + (size_t)c * 4 + qg, acc);
}

extern "C" void kernel_launch(void* const* d_in, const int* in_sizes, int n_in,
                              void* d_out, int out_size)
{
    // metadata order: vertex_dofs, edge_dofs, face_dofs, y, faces,
    //                 faces_to_edges, edge_orientation
    const float*  vertex_dofs      = (const float*) d_in[0];
    const float2* edge_dofs        = (const float2*)d_in[1];
    const float*  face_dofs        = (const float*) d_in[2];
    const float4* y                = (const float4*)d_in[3];
    const int*    faces            = (const int*)   d_in[4];
    const int*    faces_to_edges   = (const int*)   d_in[5];
    const int*    edge_orientation = (const int*)   d_in[6];
    float4*       out              = (float4*)      d_out;

    quad_fn_kernel<<<GRID, BLOCK>>>(vertex_dofs, edge_dofs, face_dofs, y,
                                    faces, faces_to_edges, edge_orientation, out);
}

// round 16
// speedup vs baseline: 1.0005x; 1.0005x over previous
#include <cuda_runtime.h>

// Problem constants (fixed by the reference)
#define C_CELLS 500000
#define NB 10
#define BLOCK 64
// 4 threads per cell, one float4 of quadrature points each.
// 2,000,000 threads = 31250 blocks of 64 exactly (no ragged block).
#define GRID 31250

__global__ __launch_bounds__(BLOCK)
void quad_fn_kernel(
    const float*  __restrict__ vertex_dofs,     // [V,1]
    const float2* __restrict__ edge_dofs,       // [E,2]
    const float*  __restrict__ face_dofs,       // [C,1]
    const float4* __restrict__ y,               // [C,NB,16] as float4 [C*40]
    const int*    __restrict__ faces,           // [C,3]
    const int*    __restrict__ faces_to_edges,  // [C,3]
    const int*    __restrict__ edge_orientation,// [C,3]
    float4*       __restrict__ out)             // [C,16] as float4 [C*4]
{
    const int gid = blockIdx.x * BLOCK + threadIdx.x;
    const int c  = gid >> 2;          // cell
    const int qg = gid & 3;           // which float4 of the 16 q-points
    if (c >= C_CELLS) return;         // never taken (exact divide), keeps safety

    // ---- Gather local dofs (identical across the 4 lanes of this cell;
    //      LSU coalesces duplicates into broadcast transactions) ----
    float d[NB];

    const int base3 = c * 3;
    #pragma unroll
    for (int i = 0; i < 3; ++i) {
        d[i] = __ldg(&vertex_dofs[__ldg(&faces[base3 + i])]);
    }
    #pragma unroll
    for (int i = 0; i < 3; ++i) {
        const int    e  = __ldg(&faces_to_edges[base3 + i]);
        const float2 ed = __ldg(&edge_dofs[e]);
        const int    o  = __ldg(&edge_orientation[base3 + i]);
        // orientation==1: keep (e0,e1); orientation==0: flipped (e1,e0)
        d[3 + 2 * i]     = o ? ed.x : ed.y;
        d[3 + 2 * i + 1] = o ? ed.y : ed.x;
    }
    d[9] = __ldg(&face_dofs[c]);

    // ---- Weighted sum over basis functions on a float4 of q-points.
    //      y is a zero-reuse 320MB stream: .cg (no L1 allocate). ----
    const float4* yp = y + (size_t)c * (NB * 4) + qg;

    float4 acc = make_float4(0.f, 0.f, 0.f, 0.f);
    #pragma unroll
    for (int b = 0; b < NB; ++b) {
        const float4 v = __ldcg(&yp[b * 4]);
        const float  w = d[b];
        acc.x = fmaf(w, v.x, acc.x);
        acc.y = fmaf(w, v.y, acc.y);
        acc.z = fmaf(w, v.z, acc.z);
        acc.w = fmaf(w, v.w, acc.w);
    }

    __stcg(out + (size_t)c * 4 + qg, acc);
}

extern "C" void kernel_launch(void* const* d_in, const int* in_sizes, int n_in,
                              void* d_out, int out_size)
{
    // metadata order: vertex_dofs, edge_dofs, face_dofs, y, faces,
    //                 faces_to_edges, edge_orientation
    const float*  vertex_dofs      = (const float*) d_in[0];
    const float2* edge_dofs        = (const float2*)d_in[1];
    const float*  face_dofs        = (const float*) d_in[2];
    const float4* y                = (const float4*)d_in[3];
    const int*    faces            = (const int*)   d_in[4];
    const int*    faces_to_edges   = (const int*)   d_in[5];
    const int*    edge_orientation = (const int*)   d_in[6];
    float4*       out              = (float4*)      d_out;

    quad_fn_kernel<<<GRID, BLOCK>>>(vertex_dofs, edge_dofs, face_dofs, y,
                                    faces, faces_to_edges, edge_orientation, out);
}

// round 17
// speedup vs baseline: 1.1086x; 1.1080x over previous
#include <cuda_runtime.h>

// Problem constants (fixed by the reference)
#define C_CELLS 500000
#define NB 10
#define BLOCK 128
// 4 threads per cell, one float4 of quadrature points each.
// 2,000,000 threads = 15625 blocks of 128 exactly (no ragged block).
#define GRID 15625

__global__ __launch_bounds__(BLOCK)
void quad_fn_kernel(
    const float*  __restrict__ vertex_dofs,     // [V,1]
    const float2* __restrict__ edge_dofs,       // [E,2]
    const float*  __restrict__ face_dofs,       // [C,1]
    const float4* __restrict__ y,               // [C,NB,16] as float4 [C*40]
    const int*    __restrict__ faces,           // [C,3]
    const int*    __restrict__ faces_to_edges,  // [C,3]
    const int*    __restrict__ edge_orientation,// [C,3]
    float4*       __restrict__ out)             // [C,16] as float4 [C*4]
{
    const int gid = blockIdx.x * BLOCK + threadIdx.x;
    const int c  = gid >> 2;          // cell
    const int qg = gid & 3;           // which float4 of the 16 q-points
    if (c >= C_CELLS) return;         // never taken (exact divide), keeps safety

    // ---- Gather local dofs (identical across the 4 lanes of this cell;
    //      LSU coalesces duplicates into broadcast transactions). Default
    //      caching: these tables are reused and should stay L1/L2-resident. ----
    float d[NB];

    const int base3 = c * 3;
    #pragma unroll
    for (int i = 0; i < 3; ++i) {
        d[i] = __ldg(&vertex_dofs[__ldg(&faces[base3 + i])]);
    }
    #pragma unroll
    for (int i = 0; i < 3; ++i) {
        const int    e  = __ldg(&faces_to_edges[base3 + i]);
        const float2 ed = __ldg(&edge_dofs[e]);
        const int    o  = __ldg(&edge_orientation[base3 + i]);
        // orientation==1: keep (e0,e1); orientation==0: flipped (e1,e0)
        d[3 + 2 * i]     = o ? ed.x : ed.y;
        d[3 + 2 * i + 1] = o ? ed.y : ed.x;
    }
    d[9] = __ldg(&face_dofs[c]);

    // ---- Weighted sum over basis functions on a float4 of q-points.
    //      y is a zero-reuse 320MB stream: .cs = evict-first in L1 AND L2,
    //      so it stops sweeping the gather tables out of L2. ----
    const float4* yp = y + (size_t)c * (NB * 4) + qg;

    float4 acc = make_float4(0.f, 0.f, 0.f, 0.f);
    #pragma unroll
    for (int b = 0; b < NB; ++b) {
        const float4 v = __ldcs(&yp[b * 4]);
        const float  w = d[b];
        acc.x = fmaf(w, v.x, acc.x);
        acc.y = fmaf(w, v.y, acc.y);
        acc.z = fmaf(w, v.z, acc.z);
        acc.w = fmaf(w, v.w, acc.w);
    }

    __stcs(out + (size_t)c * 4 + qg, acc);
}

extern "C" void kernel_launch(void* const* d_in, const int* in_sizes, int n_in,
                              void* d_out, int out_size)
{
    // metadata order: vertex_dofs, edge_dofs, face_dofs, y, faces,
    //                 faces_to_edges, edge_orientation
    const float*  vertex_dofs      = (const float*) d_in[0];
    const float2* edge_dofs        = (const float2*)d_in[1];
    const float*  face_dofs        = (const float*) d_in[2];
    const float4* y                = (const float4*)d_in[3];
    const int*    faces            = (const int*)   d_in[4];
    const int*    faces_to_edges   = (const int*)   d_in[5];
    const int*    edge_orientation = (const int*)   d_in[6];
    float4*       out              = (float4*)      d_out;

    quad_fn_kernel<<<GRID, BLOCK>>>(vertex_dofs, edge_dofs, face_dofs, y,
                                    faces, faces_to_edges, edge_orientation, out);
}